// round 11
// baseline (speedup 1.0000x reference)
#include <cuda_runtime.h>
#include <cuda_bf16.h>
#include <math.h>

#define Bsz 256
#define Tsz 512
#define Isz 128
#define Hsz 256
#define H2  512
#define NBLK 128
#define NTHR 512
#define CTHR 256
#define PAD 65

typedef unsigned long long u64;

// ---------------- static device scratch (no allocation) ----------------
__device__ float g_c[Bsz * Hsz];
__device__ float g_h[Bsz * Hsz];
__device__ float g_gru[Bsz * Hsz];
__device__ float g_a1[Bsz * H2];
__device__ float g_a2[Bsz * H2];
__device__ float g_n[Bsz];
__device__ float g_logit[Bsz];
__device__ unsigned g_cnt[4 * 32];   // one counter per rowgroup, 128B apart
__device__ unsigned g_gen[4 * 32];

// ---------------- f32x2 packed helpers ----------------------------------
__device__ __forceinline__ u64 pack2(float lo, float hi) {
    u64 r; asm("mov.b64 %0, {%1,%2};" : "=l"(r) : "f"(lo), "f"(hi)); return r;
}
__device__ __forceinline__ float sum2(u64 v) {
    float lo, hi; asm("mov.b64 {%0,%1}, %2;" : "=f"(lo), "=f"(hi) : "l"(v));
    return lo + hi;
}
__device__ __forceinline__ void fma2(u64& d, u64 a, u64 b) {
    asm("fma.rn.f32x2 %0, %1, %2, %0;" : "+l"(d) : "l"(a), "l"(b));
}

// ---------------- per-rowgroup barrier (32 co-resident blocks) -----------
__device__ __forceinline__ void rg_sync(int rg) {
    __syncthreads();
    if (threadIdx.x == 0) {
        __threadfence();
        unsigned* cnt = &g_cnt[rg * 32];
        unsigned* gen = &g_gen[rg * 32];
        unsigned g = *((volatile unsigned*)gen);
        if (atomicAdd(cnt, 1u) == 31u) {
            atomicExch(cnt, 0u);
            __threadfence();
            atomicAdd(gen, 1u);
        } else {
            while (*((volatile unsigned*)gen) == g) { __nanosleep(32); }
        }
        __threadfence();
    }
    __syncthreads();
}

// ---------------- chunk staging: 64 rows x 64 k, swizzled SMEM -----------
// word layout: row*64 + (k ^ (((row>>1)&7)<<2))  -> conflict-free LDS.128
__device__ __forceinline__ void ldg_chunk(float4* pre, const float* __restrict__ gsrc,
                                          size_t gstride, int r0, int k0, int tid) {
#pragma unroll
    for (int i = 0; i < 2; i++) {
        int q = tid + i * NTHR;           // float4 index 0..1023
        int row = q >> 4;
        int k = (q & 15) << 2;
        pre[i] = __ldcg((const float4*)(gsrc + (size_t)(r0 + row) * gstride + k0 + k));
    }
}
__device__ __forceinline__ void sts_chunk(float* sbuf, const float4* pre, int tid) {
#pragma unroll
    for (int i = 0; i < 2; i++) {
        int q = tid + i * NTHR;
        int row = q >> 4;
        unsigned k = (unsigned)((q & 15) << 2);
        unsigned swz = (((unsigned)row >> 1) & 7u) << 2;
        *(float4*)(sbuf + row * 64 + (k ^ swz)) = pre[i];
    }
}

// ---------------- full MLP stage: 64 rows x (2 rows x 1 col)/thread ------
// chunks c < splitc read (srcA, strA), else (srcB, strB).
template <int STORE>
__device__ __forceinline__ void mlp_stage(
    const float* __restrict__ srcA, size_t strA,
    const float* __restrict__ srcB, size_t strB, int splitc,
    const float* sW, const float* __restrict__ bias, const float* __restrict__ W4,
    float* __restrict__ dst, float* buf0, float* buf1, float* s_part,
    int r0, int j0, int tid)
{
    const int rl = (tid & 31) * 2;
    const int jl = tid >> 5;            // 0..15, warp-uniform
    const int j = j0 + jl;
    const unsigned swz = (((unsigned)rl >> 1) & 7u) << 2;
    const float* wrow = sW + (size_t)jl * H2;
    u64 acc0 = pack2(bias[j], 0.f);
    u64 acc1 = acc0;

    float4 pre[2];
    {
        const float* s = (0 < splitc) ? srcA : srcB;
        size_t st = (0 < splitc) ? strA : strB;
        ldg_chunk(pre, s, st, r0, 0, tid);
    }
#pragma unroll 1
    for (int c = 0; c < 8; c++) {
        float* cb = (c & 1) ? buf1 : buf0;
        sts_chunk(cb, pre, tid);
        if (c + 1 < 8) {
            const float* s = (c + 1 < splitc) ? srcA : srcB;
            size_t st = (c + 1 < splitc) ? strA : strB;
            ldg_chunk(pre, s, st, r0, (c + 1) * 64, tid);
        }
        __syncthreads();
        const float* a0 = cb + rl * 64;
        const float* a1 = a0 + 64;
        const float* wk = wrow + c * 64;
#pragma unroll
        for (int kk = 0; kk < 64; kk += 4) {
            ulonglong2 w = *(const ulonglong2*)(wk + kk);
            ulonglong2 x0 = *(const ulonglong2*)(a0 + ((unsigned)kk ^ swz));
            ulonglong2 x1 = *(const ulonglong2*)(a1 + ((unsigned)kk ^ swz));
            fma2(acc0, x0.x, w.x); fma2(acc0, x0.y, w.y);
            fma2(acc1, x1.x, w.x); fma2(acc1, x1.y, w.y);
        }
        __syncthreads();
    }
    float v0 = fmaxf(sum2(acc0), 0.f);
    float v1 = fmaxf(sum2(acc1), 0.f);
    const int b0 = r0 + rl;
    if (STORE) {
        dst[(size_t)b0 * H2 + j] = v0;
        dst[(size_t)(b0 + 1) * H2 + j] = v1;
    } else {
        float w4 = W4[j];
        atomicAdd(&s_part[rl], v0 * w4);
        atomicAdd(&s_part[rl + 1], v1 * w4);
    }
}

// ---------------- GRU: side-split. warps 0-7: input-side (c), 8-15: h ----
__device__ __forceinline__ void gru_stage(
    const float* sWih, const float* sWhh,
    const float* __restrict__ bih, const float* __restrict__ bhh,
    float* buf0, float* buf1, float* buf2, float* buf3, float* s_gru,
    int r0, int jh0, int tid, float* __restrict__ dst)
{
    const int side = tid >> 8;          // 0: input-side, 1: hidden-side
    const int sub = tid & 255;
    const int rl = (sub & 31) * 2;
    const int jl = sub >> 5;            // 0..7, warp-uniform
    const int jh = jh0 + jl;
    const unsigned swz = (((unsigned)rl >> 1) & 7u) << 2;
    const float* sw = side ? sWhh : sWih;
    const float* bb = side ? bhh : bih;
    const float* wR = sw + (size_t)jl * Hsz;
    const float* wZ = sw + (size_t)(8 + jl) * Hsz;
    const float* wN = sw + (size_t)(16 + jl) * Hsz;
    u64 aR0 = pack2(bb[jh], 0.f);
    u64 aZ0 = pack2(bb[jh + Hsz], 0.f);
    u64 aN0 = pack2(bb[jh + 2 * Hsz], 0.f);
    u64 aR1 = aR0, aZ1 = aZ0, aN1 = aN0;

    float4 prec[2], preh[2];
    ldg_chunk(prec, g_c, Hsz, r0, 0, tid);
    ldg_chunk(preh, g_h, Hsz, r0, 0, tid);
#pragma unroll 1
    for (int c = 0; c < 4; c++) {
        float* cb = (c & 1) ? buf1 : buf0;
        float* hb = (c & 1) ? buf3 : buf2;
        sts_chunk(cb, prec, tid);
        sts_chunk(hb, preh, tid);
        if (c + 1 < 4) {
            ldg_chunk(prec, g_c, Hsz, r0, (c + 1) * 64, tid);
            ldg_chunk(preh, g_h, Hsz, r0, (c + 1) * 64, tid);
        }
        __syncthreads();
        const float* base = side ? hb : cb;
        const float* a0 = base + rl * 64;
        const float* a1 = a0 + 64;
        const int k0 = c * 64;
#pragma unroll
        for (int kk = 0; kk < 64; kk += 4) {
            ulonglong2 wr = *(const ulonglong2*)(wR + k0 + kk);
            ulonglong2 wz = *(const ulonglong2*)(wZ + k0 + kk);
            ulonglong2 wn = *(const ulonglong2*)(wN + k0 + kk);
            ulonglong2 x0 = *(const ulonglong2*)(a0 + ((unsigned)kk ^ swz));
            ulonglong2 x1 = *(const ulonglong2*)(a1 + ((unsigned)kk ^ swz));
            fma2(aR0, x0.x, wr.x); fma2(aR0, x0.y, wr.y);
            fma2(aZ0, x0.x, wz.x); fma2(aZ0, x0.y, wz.y);
            fma2(aN0, x0.x, wn.x); fma2(aN0, x0.y, wn.y);
            fma2(aR1, x1.x, wr.x); fma2(aR1, x1.y, wr.y);
            fma2(aZ1, x1.x, wz.x); fma2(aZ1, x1.y, wz.y);
            fma2(aN1, x1.x, wn.x); fma2(aN1, x1.y, wn.y);
        }
        __syncthreads();
    }
    if (side == 1) {
        s_gru[(0 * 8 + jl) * 64 + rl]     = sum2(aR0);
        s_gru[(0 * 8 + jl) * 64 + rl + 1] = sum2(aR1);
        s_gru[(8 + jl) * 64 + rl]         = sum2(aZ0);
        s_gru[(8 + jl) * 64 + rl + 1]     = sum2(aZ1);
        s_gru[(16 + jl) * 64 + rl]        = sum2(aN0);
        s_gru[(16 + jl) * 64 + rl + 1]    = sum2(aN1);
    }
    __syncthreads();
    if (side == 0) {
        const int b0 = r0 + rl;
        float hv0 = __ldcg(&g_h[b0 * Hsz + jh]);
        float hv1 = __ldcg(&g_h[(b0 + 1) * Hsz + jh]);
        float hr0 = s_gru[(0 * 8 + jl) * 64 + rl];
        float hr1 = s_gru[(0 * 8 + jl) * 64 + rl + 1];
        float hz0 = s_gru[(8 + jl) * 64 + rl];
        float hz1 = s_gru[(8 + jl) * 64 + rl + 1];
        float hn0 = s_gru[(16 + jl) * 64 + rl];
        float hn1 = s_gru[(16 + jl) * 64 + rl + 1];
        float R0 = 1.f / (1.f + expf(-(sum2(aR0) + hr0)));
        float Z0 = 1.f / (1.f + expf(-(sum2(aZ0) + hz0)));
        float N0 = tanhf(sum2(aN0) + R0 * hn0);
        dst[(size_t)b0 * Hsz + jh] = (1.f - Z0) * N0 + Z0 * hv0;
        float R1 = 1.f / (1.f + expf(-(sum2(aR1) + hr1)));
        float Z1 = 1.f / (1.f + expf(-(sum2(aZ1) + hz1)));
        float N1 = tanhf(sum2(aN1) + R1 * hn1);
        dst[(size_t)(b0 + 1) * Hsz + jh] = (1.f - Z1) * N1 + Z1 * hv1;
    }
    __syncthreads();
}

// ---------------- precompute c_concat = tanh(X @ W_cin^T) ----------------
__global__ void __launch_bounds__(CTHR) cin_kernel(
    const float* __restrict__ X, const float* __restrict__ Wc,
    const float* __restrict__ bc, float* __restrict__ outC)
{
    __shared__ float sA[64 * PAD];
    const int tid = threadIdx.x;
    const int blk = blockIdx.x;
    const int rg = blk >> 4, cg = blk & 15;
    const int r0 = rg * 64;
    const int rl = (tid & 31) * 2;
    const int j = cg * 16 + (tid >> 5) * 2;
    float acc00 = bc[j], acc01 = bc[j + 1];
    float acc10 = acc00, acc11 = acc01;
    const float* wp0 = Wc + (size_t)j * Isz;
    const float* wp1 = Wc + (size_t)(j + 1) * Isz;
    for (int k0 = 0; k0 < Isz; k0 += 64) {
#pragma unroll
        for (int i = 0; i < 16; i++) {
            int idx = tid + i * CTHR;
            int rr = idx >> 6;
            int kk = idx & 63;
            sA[rr * PAD + kk] = X[(size_t)(r0 + rr) * Isz + k0 + kk];
        }
        __syncthreads();
        const float* a0 = sA + rl * PAD;
        const float* a1 = a0 + PAD;
#pragma unroll
        for (int kk = 0; kk < 64; kk++) {
            float w0 = wp0[k0 + kk], w1 = wp1[k0 + kk];
            acc00 = fmaf(a0[kk], w0, acc00);
            acc01 = fmaf(a0[kk], w1, acc01);
            acc10 = fmaf(a1[kk], w0, acc10);
            acc11 = fmaf(a1[kk], w1, acc11);
        }
        __syncthreads();
    }
    const size_t m0 = (size_t)(r0 + rl);
    outC[m0 * Hsz + j] = tanhf(acc00);
    outC[m0 * Hsz + j + 1] = tanhf(acc01);
    outC[(m0 + 1) * Hsz + j] = tanhf(acc10);
    outC[(m0 + 1) * Hsz + j + 1] = tanhf(acc11);
}

// ---------------- persistent recurrent kernel ----------------------------
#define SMEM_FLOATS (3 * 16 * H2 + 2 * 24 * Hsz + 4 * 4096)
#define SMEM_BYTES (SMEM_FLOATS * 4)

__global__ void __launch_bounds__(NTHR, 1) rnn_kernel(
    const float* __restrict__ noise,
    const float* __restrict__ W1, const float* __restrict__ b1,
    const float* __restrict__ W2, const float* __restrict__ b2,
    const float* __restrict__ W3, const float* __restrict__ b3,
    const float* __restrict__ W4, const float* __restrict__ b4,
    const float* __restrict__ Wih, const float* __restrict__ Whh,
    const float* __restrict__ bih, const float* __restrict__ bhh,
    float* out)
{
    extern __shared__ float smem[];
    float* sW1 = smem;
    float* sW2 = sW1 + 16 * H2;
    float* sW3 = sW2 + 16 * H2;
    float* sWih = sW3 + 16 * H2;
    float* sWhh = sWih + 24 * Hsz;
    float* buf0 = sWhh + 24 * Hsz;
    float* buf1 = buf0 + 4096;
    float* buf2 = buf1 + 4096;
    float* buf3 = buf2 + 4096;
    __shared__ float s_part[64];
    __shared__ float s_gru[24 * 64];

    const int tid = threadIdx.x;
    const int blk = blockIdx.x;
    const int rg = blk >> 5, cg = blk & 31;
    const int r0 = rg * 64;
    const int j0 = cg * 16;
    const int jh0 = cg * 8;
    float* outC = out;
    float* outH = out + (size_t)Bsz * Tsz * Hsz;
    float* outF = outH + (size_t)Bsz * Tsz * Hsz;

    // ---- preload this block's weight slices into SMEM (once) ----
    {
        const float* Wg[3] = {W1, W2, W3};
        float* sWd[3] = {sW1, sW2, sW3};
#pragma unroll 1
        for (int m = 0; m < 3; m++) {
            for (int i = tid; i < 2048; i += NTHR) {   // float4 count
                int col = i >> 7, k4 = i & 127;
                ((float4*)sWd[m])[col * 128 + k4] =
                    __ldg((const float4*)(Wg[m] + (size_t)(j0 + col) * H2) + k4);
            }
        }
        for (int i = tid; i < 1536; i += NTHR) {       // 24 rows x 64 f4
            int rr = i >> 6, k4 = i & 63;
            int gte = rr >> 3, cl = rr & 7;
            size_t grow = (size_t)(gte * Hsz + jh0 + cl) * Hsz;
            ((float4*)sWih)[rr * 64 + k4] = __ldg((const float4*)(Wih + grow) + k4);
            ((float4*)sWhh)[rr * 64 + k4] = __ldg((const float4*)(Whh + grow) + k4);
        }
    }

    // ---- init state (each block owns batch rows 2blk, 2blk+1) ----
    {
        int b = 2 * blk + (tid >> 8);
        int jj = tid & 255;
        g_c[b * Hsz + jj] = 0.f;
        g_h[b * Hsz + jj] = 0.f;
        if (jj == 0) { g_n[b] = 0.f; g_logit[b] = b4[0]; }
    }
    rg_sync(rg);

    const size_t cstr = (size_t)Tsz * Hsz;
#pragma unroll 1
    for (int t = 0; t < Tsz; t++) {
        // ---- stage 1: a1 = relu([c, c_in] @ W1^T + b1)  +  GRU(c,h) ----
        mlp_stage<1>(g_c, (size_t)Hsz, outC + (size_t)t * Hsz - 256, cstr, 4,
                     sW1, b1, (const float*)0, g_a1, buf0, buf1, s_part, r0, j0, tid);
        gru_stage(sWih, sWhh, bih, bhh, buf0, buf1, buf2, buf3, s_gru,
                  r0, jh0, tid, g_gru);
        rg_sync(rg);
        // ---- stage 2: a2 ----
        mlp_stage<1>(g_a1, (size_t)H2, g_a1, (size_t)H2, 8,
                     sW2, b2, (const float*)0, g_a2, buf0, buf1, s_part, r0, j0, tid);
        rg_sync(rg);
        // ---- stage 3: a3 reduced against W4 -> logit ----
        if (tid < 64) s_part[tid] = 0.f;
        __syncthreads();
        mlp_stage<0>(g_a2, (size_t)H2, g_a2, (size_t)H2, 8,
                     sW3, b3, W4, (float*)0, buf0, buf1, s_part, r0, j0, tid);
        __syncthreads();
        if (tid < 64) atomicAdd(&g_logit[r0 + tid], s_part[tid]);
        rg_sync(rg);
        // ---- stage 4: gate + state update (own 2 batch rows) ----
        {
            int b = 2 * blk + (tid >> 8);
            int jj = tid & 255;
            float logit = __ldcg(&g_logit[b]);
            float u = noise[(size_t)t * Bsz + b];
            float lg = logf(u) - log1pf(-u);
            float alpha = 1.f / (1.f + expf(-(logit + lg) * 10.f));
            float oma = 1.f - alpha;
            float nold = g_n[b];
            float nnew = nold * oma + 1.f;
            float inv = 1.f / nnew;
            float cin = outC[(size_t)b * cstr + (size_t)t * Hsz + jj];
            float cold = g_c[b * Hsz + jj];
            float hold = g_h[b * Hsz + jj];
            float gr = __ldcg(&g_gru[b * Hsz + jj]);
            float hnew = hold * oma + alpha * gr;
            float cnew = (cold * nold * oma + cin) * inv;
            g_c[b * Hsz + jj] = cnew;
            g_h[b * Hsz + jj] = hnew;
            outH[(size_t)b * cstr + (size_t)t * Hsz + jj] = hnew;
            if (jj == 0) { g_n[b] = nnew; g_logit[b] = b4[0]; }
        }
        rg_sync(rg);
    }
    // ---- h_final = GRUCell(c_T, h_T) ----
    gru_stage(sWih, sWhh, bih, bhh, buf0, buf1, buf2, buf3, s_gru,
              r0, jh0, tid, outF);
}

extern "C" void kernel_launch(void* const* d_in, const int* in_sizes, int n_in,
                              void* d_out, int out_size)
{
    const float* input = (const float*)d_in[0];
    const float* noise = (const float*)d_in[1];
    const float* W_cin = (const float*)d_in[2];
    const float* b_cin = (const float*)d_in[3];
    const float* W1 = (const float*)d_in[4];
    const float* b1 = (const float*)d_in[5];
    const float* W2 = (const float*)d_in[6];
    const float* b2 = (const float*)d_in[7];
    const float* W3 = (const float*)d_in[8];
    const float* b3 = (const float*)d_in[9];
    const float* W4 = (const float*)d_in[10];
    const float* b4 = (const float*)d_in[11];
    const float* Wih = (const float*)d_in[12];
    const float* Whh = (const float*)d_in[13];
    const float* bih = (const float*)d_in[14];
    const float* bhh = (const float*)d_in[15];
    float* out = (float*)d_out;

    cudaFuncSetAttribute(rnn_kernel, cudaFuncAttributeMaxDynamicSharedMemorySize,
                         SMEM_BYTES);

    // c_concat = tanh(input @ W_cin^T + b_cin), written straight into d_out
    cin_kernel<<<(Bsz * Tsz / 64) * (Hsz / 16), CTHR>>>(input, W_cin, b_cin, out);
    // persistent recurrent kernel (reads c_concat back as the c_in stream)
    rnn_kernel<<<NBLK, NTHR, SMEM_BYTES>>>(noise, W1, b1, W2, b2, W3, b3, W4, b4,
                                           Wih, Whh, bih, bhh, out);
}

// round 13
// speedup vs baseline: 1.4788x; 1.4788x over previous
#include <cuda_runtime.h>
#include <cuda_bf16.h>
#include <math.h>

#define Bsz 256
#define Tsz 512
#define Isz 128
#define Hsz 256
#define H2  512
#define NBLK 128
#define NTHR 256
#define CTHR 256
#define CH 128
#define PAD 65

typedef unsigned long long u64;

// ---------------- static device scratch (no allocation) ----------------
__device__ float g_c[Bsz * Hsz];
__device__ float g_h[Bsz * Hsz];
__device__ float g_gru[Bsz * Hsz];
__device__ float g_a1[Bsz * H2];
__device__ float g_a2[Bsz * H2];
__device__ float g_n[Bsz];
__device__ float g_logit[Bsz];
__device__ unsigned g_cnt[4 * 32];
__device__ unsigned g_gen[4 * 32];

// ---------------- f32x2 packed helpers ----------------------------------
__device__ __forceinline__ u64 pack2(float lo, float hi) {
    u64 r; asm("mov.b64 %0, {%1,%2};" : "=l"(r) : "f"(lo), "f"(hi)); return r;
}
__device__ __forceinline__ float sum2(u64 v) {
    float lo, hi; asm("mov.b64 {%0,%1}, %2;" : "=f"(lo), "=f"(hi) : "l"(v));
    return lo + hi;
}
__device__ __forceinline__ void fma2(u64& d, u64 a, u64 b) {
    asm("fma.rn.f32x2 %0, %1, %2, %0;" : "+l"(d) : "l"(a), "l"(b));
}

// ---------------- per-rowgroup barrier (32 co-resident blocks) -----------
__device__ __forceinline__ void rg_sync(int rg) {
    __syncthreads();
    if (threadIdx.x == 0) {
        __threadfence();
        unsigned* cnt = &g_cnt[rg * 32];
        unsigned* gen = &g_gen[rg * 32];
        unsigned g = *((volatile unsigned*)gen);
        if (atomicAdd(cnt, 1u) == 31u) {
            atomicExch(cnt, 0u);
            __threadfence();
            atomicAdd(gen, 1u);
        } else {
            while (*((volatile unsigned*)gen) == g) { __nanosleep(32); }
        }
        __threadfence();
    }
    __syncthreads();
}

__device__ __forceinline__ unsigned swz_of(int row) {
    return (((unsigned)row >> 1) & 7u) << 2;
}

// ---------------- stage one 64-row x 128-k chunk into swizzled SMEM ------
__device__ __forceinline__ void stage_chunk(float* sbuf, const float* __restrict__ src,
                                            size_t str, int r0, int k0, int tid) {
#pragma unroll
    for (int i = 0; i < 8; i++) {
        int q = tid + i * NTHR;
        int row = q >> 5;
        int kf = (q & 31) << 2;
        float4 v = __ldcg((const float4*)(src + (size_t)(r0 + row) * str + k0 + kf));
        *(float4*)(sbuf + row * CH + (kf ^ swz_of(row))) = v;
    }
}

// ---------------- MLP stage: 64 rows x 16 cols, C=4, k-split 2 -----------
// src0: k 0..255 (row stride str0), src1: k 256..511 (row stride str1)
template <int STORE>
__device__ __forceinline__ void mlp_stage(
    const float* __restrict__ src0, size_t str0,
    const float* __restrict__ src1, size_t str1,
    const float* sW, const float* __restrict__ bias, const float* __restrict__ W4,
    float* __restrict__ dst, float* buf0, float* buf1, float* s_red, float* s_part,
    int r0, int j0, int tid)
{
    const int lane = tid & 31;
    const int w = tid >> 5;
    const int half = w >> 2;            // 0: k 0..255, 1: k 256..511
    const int cg = w & 3;               // col group (4 cols each)
    const int rl = lane * 2;
    const unsigned swz = ((unsigned)lane & 7u) << 2;
    const int j = j0 + cg * 4;
    const float* wr0 = sW + (size_t)(cg * 4 + 0) * H2 + half * 256;
    const float* wr1 = sW + (size_t)(cg * 4 + 1) * H2 + half * 256;
    const float* wr2 = sW + (size_t)(cg * 4 + 2) * H2 + half * 256;
    const float* wr3 = sW + (size_t)(cg * 4 + 3) * H2 + half * 256;

    u64 a00, a01, a02, a03, a10, a11, a12, a13;
    if (half == 0) {
        a00 = pack2(bias[j], 0.f);     a01 = pack2(bias[j + 1], 0.f);
        a02 = pack2(bias[j + 2], 0.f); a03 = pack2(bias[j + 3], 0.f);
    } else {
        a00 = 0; a01 = 0; a02 = 0; a03 = 0;
    }
    a10 = a00; a11 = a01; a12 = a02; a13 = a03;
    const float* mybuf = half ? buf1 : buf0;

#pragma unroll 1
    for (int ci = 0; ci < 2; ci++) {
        stage_chunk(buf0, src0, str0, r0, ci * CH, tid);
        stage_chunk(buf1, src1, str1, r0, ci * CH, tid);
        __syncthreads();
        const float* a0 = mybuf + rl * CH;
        const float* a1 = a0 + CH;
        const float* k0p = wr0 + ci * CH;
        const float* k1p = wr1 + ci * CH;
        const float* k2p = wr2 + ci * CH;
        const float* k3p = wr3 + ci * CH;
#pragma unroll
        for (int kk = 0; kk < CH; kk += 4) {
            ulonglong2 x0 = *(const ulonglong2*)(a0 + ((unsigned)kk ^ swz));
            ulonglong2 x1 = *(const ulonglong2*)(a1 + ((unsigned)kk ^ swz));
            ulonglong2 w0 = *(const ulonglong2*)(k0p + kk);
            ulonglong2 w1 = *(const ulonglong2*)(k1p + kk);
            ulonglong2 w2 = *(const ulonglong2*)(k2p + kk);
            ulonglong2 w3 = *(const ulonglong2*)(k3p + kk);
            fma2(a00, x0.x, w0.x); fma2(a00, x0.y, w0.y);
            fma2(a01, x0.x, w1.x); fma2(a01, x0.y, w1.y);
            fma2(a02, x0.x, w2.x); fma2(a02, x0.y, w2.y);
            fma2(a03, x0.x, w3.x); fma2(a03, x0.y, w3.y);
            fma2(a10, x1.x, w0.x); fma2(a10, x1.y, w0.y);
            fma2(a11, x1.x, w1.x); fma2(a11, x1.y, w1.y);
            fma2(a12, x1.x, w2.x); fma2(a12, x1.y, w2.y);
            fma2(a13, x1.x, w3.x); fma2(a13, x1.y, w3.y);
        }
        __syncthreads();
    }
    // combine the two k-halves
    if (half == 1) {
        float4 p0 = make_float4(sum2(a00), sum2(a01), sum2(a02), sum2(a03));
        float4 p1 = make_float4(sum2(a10), sum2(a11), sum2(a12), sum2(a13));
        ((float4*)s_red)[(cg * 32 + lane) * 2 + 0] = p0;
        ((float4*)s_red)[(cg * 32 + lane) * 2 + 1] = p1;
    }
    __syncthreads();
    if (half == 0) {
        float4 p0 = ((float4*)s_red)[(cg * 32 + lane) * 2 + 0];
        float4 p1 = ((float4*)s_red)[(cg * 32 + lane) * 2 + 1];
        float4 v0, v1;
        v0.x = fmaxf(sum2(a00) + p0.x, 0.f);
        v0.y = fmaxf(sum2(a01) + p0.y, 0.f);
        v0.z = fmaxf(sum2(a02) + p0.z, 0.f);
        v0.w = fmaxf(sum2(a03) + p0.w, 0.f);
        v1.x = fmaxf(sum2(a10) + p1.x, 0.f);
        v1.y = fmaxf(sum2(a11) + p1.y, 0.f);
        v1.z = fmaxf(sum2(a12) + p1.z, 0.f);
        v1.w = fmaxf(sum2(a13) + p1.w, 0.f);
        const int b0 = r0 + rl;
        if (STORE) {
            *(float4*)(dst + (size_t)b0 * H2 + j) = v0;
            *(float4*)(dst + (size_t)(b0 + 1) * H2 + j) = v1;
        } else {
            float4 w4 = *(const float4*)(W4 + j);
            atomicAdd(&s_part[rl], v0.x * w4.x + v0.y * w4.y + v0.z * w4.z + v0.w * w4.w);
            atomicAdd(&s_part[rl + 1], v1.x * w4.x + v1.y * w4.y + v1.z * w4.z + v1.w * w4.w);
        }
    }
    __syncthreads();
}

// ---------------- GRU: side-split (warps 0-3 input, 4-7 hidden) ----------
// each warp: 2 cols x 3 gates x 2 rows = 12 accumulators, k=256
__device__ __forceinline__ void gru_stage(
    const float* sWih, const float* sWhh,
    const float* __restrict__ bih, const float* __restrict__ bhh,
    float* bufC, float* bufH, float* s_red,
    int r0, int jh0, int tid, float* __restrict__ dst)
{
    const int lane = tid & 31;
    const int w = tid >> 5;
    const int side = w >> 2;
    const int cg = w & 3;
    const int rl = lane * 2;
    const unsigned swz = ((unsigned)lane & 7u) << 2;
    const int jl = cg * 2;
    const float* base = side ? sWhh : sWih;
    const float* bb = side ? bhh : bih;
    const float* wR0 = base + (size_t)(0 * 8 + jl) * Hsz;
    const float* wR1 = base + (size_t)(0 * 8 + jl + 1) * Hsz;
    const float* wZ0 = base + (size_t)(1 * 8 + jl) * Hsz;
    const float* wZ1 = base + (size_t)(1 * 8 + jl + 1) * Hsz;
    const float* wN0 = base + (size_t)(2 * 8 + jl) * Hsz;
    const float* wN1 = base + (size_t)(2 * 8 + jl + 1) * Hsz;
    const int jh = jh0 + jl;
    u64 R00 = pack2(bb[jh], 0.f),        R01 = pack2(bb[jh + 1], 0.f);
    u64 Z00 = pack2(bb[Hsz + jh], 0.f),  Z01 = pack2(bb[Hsz + jh + 1], 0.f);
    u64 N00 = pack2(bb[2 * Hsz + jh], 0.f), N01 = pack2(bb[2 * Hsz + jh + 1], 0.f);
    u64 R10 = R00, R11 = R01, Z10 = Z00, Z11 = Z01, N10 = N00, N11 = N01;

#pragma unroll 1
    for (int ci = 0; ci < 2; ci++) {
        stage_chunk(bufC, g_c, Hsz, r0, ci * CH, tid);
        stage_chunk(bufH, g_h, Hsz, r0, ci * CH, tid);
        __syncthreads();
        const float* mb = side ? bufH : bufC;
        const float* a0 = mb + rl * CH;
        const float* a1 = a0 + CH;
#pragma unroll
        for (int kk = 0; kk < CH; kk += 4) {
            ulonglong2 x0 = *(const ulonglong2*)(a0 + ((unsigned)kk ^ swz));
            ulonglong2 x1 = *(const ulonglong2*)(a1 + ((unsigned)kk ^ swz));
            ulonglong2 r0w = *(const ulonglong2*)(wR0 + ci * CH + kk);
            ulonglong2 r1w = *(const ulonglong2*)(wR1 + ci * CH + kk);
            ulonglong2 z0w = *(const ulonglong2*)(wZ0 + ci * CH + kk);
            ulonglong2 z1w = *(const ulonglong2*)(wZ1 + ci * CH + kk);
            ulonglong2 n0w = *(const ulonglong2*)(wN0 + ci * CH + kk);
            ulonglong2 n1w = *(const ulonglong2*)(wN1 + ci * CH + kk);
            fma2(R00, x0.x, r0w.x); fma2(R00, x0.y, r0w.y);
            fma2(R01, x0.x, r1w.x); fma2(R01, x0.y, r1w.y);
            fma2(Z00, x0.x, z0w.x); fma2(Z00, x0.y, z0w.y);
            fma2(Z01, x0.x, z1w.x); fma2(Z01, x0.y, z1w.y);
            fma2(N00, x0.x, n0w.x); fma2(N00, x0.y, n0w.y);
            fma2(N01, x0.x, n1w.x); fma2(N01, x0.y, n1w.y);
            fma2(R10, x1.x, r0w.x); fma2(R10, x1.y, r0w.y);
            fma2(R11, x1.x, r1w.x); fma2(R11, x1.y, r1w.y);
            fma2(Z10, x1.x, z0w.x); fma2(Z10, x1.y, z0w.y);
            fma2(Z11, x1.x, z1w.x); fma2(Z11, x1.y, z1w.y);
            fma2(N10, x1.x, n0w.x); fma2(N10, x1.y, n0w.y);
            fma2(N11, x1.x, n1w.x); fma2(N11, x1.y, n1w.y);
        }
        __syncthreads();
    }
    if (side == 1) {
        float* p = s_red + (cg * 32 + lane) * 12;
        p[0] = sum2(R00); p[1] = sum2(R01);
        p[2] = sum2(Z00); p[3] = sum2(Z01);
        p[4] = sum2(N00); p[5] = sum2(N01);
        p[6] = sum2(R10); p[7] = sum2(R11);
        p[8] = sum2(Z10); p[9] = sum2(Z11);
        p[10] = sum2(N10); p[11] = sum2(N11);
    }
    __syncthreads();
    if (side == 0) {
        const float* p = s_red + (cg * 32 + lane) * 12;
        const int b0 = r0 + rl;
        {
            float Rg = 1.f / (1.f + expf(-(sum2(R00) + p[0])));
            float Zg = 1.f / (1.f + expf(-(sum2(Z00) + p[2])));
            float Ng = tanhf(sum2(N00) + Rg * p[4]);
            float ho = __ldcg(&g_h[b0 * Hsz + jh]);
            dst[(size_t)b0 * Hsz + jh] = (1.f - Zg) * Ng + Zg * ho;
        }
        {
            float Rg = 1.f / (1.f + expf(-(sum2(R01) + p[1])));
            float Zg = 1.f / (1.f + expf(-(sum2(Z01) + p[3])));
            float Ng = tanhf(sum2(N01) + Rg * p[5]);
            float ho = __ldcg(&g_h[b0 * Hsz + jh + 1]);
            dst[(size_t)b0 * Hsz + jh + 1] = (1.f - Zg) * Ng + Zg * ho;
        }
        {
            float Rg = 1.f / (1.f + expf(-(sum2(R10) + p[6])));
            float Zg = 1.f / (1.f + expf(-(sum2(Z10) + p[8])));
            float Ng = tanhf(sum2(N10) + Rg * p[10]);
            float ho = __ldcg(&g_h[(b0 + 1) * Hsz + jh]);
            dst[(size_t)(b0 + 1) * Hsz + jh] = (1.f - Zg) * Ng + Zg * ho;
        }
        {
            float Rg = 1.f / (1.f + expf(-(sum2(R11) + p[7])));
            float Zg = 1.f / (1.f + expf(-(sum2(Z11) + p[9])));
            float Ng = tanhf(sum2(N11) + Rg * p[11]);
            float ho = __ldcg(&g_h[(b0 + 1) * Hsz + jh + 1]);
            dst[(size_t)(b0 + 1) * Hsz + jh + 1] = (1.f - Zg) * Ng + Zg * ho;
        }
    }
    __syncthreads();
}

// ---------------- precompute c_concat = tanh(X @ W_cin^T) ----------------
__global__ void __launch_bounds__(CTHR) cin_kernel(
    const float* __restrict__ X, const float* __restrict__ Wc,
    const float* __restrict__ bc, float* __restrict__ outC)
{
    __shared__ float sA[64 * PAD];
    const int tid = threadIdx.x;
    const int blk = blockIdx.x;
    const int rg = blk >> 4, cg = blk & 15;
    const int r0 = rg * 64;
    const int rl = (tid & 31) * 2;
    const int j = cg * 16 + (tid >> 5) * 2;
    float acc00 = bc[j], acc01 = bc[j + 1];
    float acc10 = acc00, acc11 = acc01;
    const float* wp0 = Wc + (size_t)j * Isz;
    const float* wp1 = Wc + (size_t)(j + 1) * Isz;
    for (int k0 = 0; k0 < Isz; k0 += 64) {
#pragma unroll
        for (int i = 0; i < 16; i++) {
            int idx = tid + i * CTHR;
            int rr = idx >> 6;
            int kk = idx & 63;
            sA[rr * PAD + kk] = X[(size_t)(r0 + rr) * Isz + k0 + kk];
        }
        __syncthreads();
        const float* a0 = sA + rl * PAD;
        const float* a1 = a0 + PAD;
#pragma unroll
        for (int kk = 0; kk < 64; kk++) {
            float w0 = wp0[k0 + kk], w1 = wp1[k0 + kk];
            acc00 = fmaf(a0[kk], w0, acc00);
            acc01 = fmaf(a0[kk], w1, acc01);
            acc10 = fmaf(a1[kk], w0, acc10);
            acc11 = fmaf(a1[kk], w1, acc11);
        }
        __syncthreads();
    }
    const size_t m0 = (size_t)(r0 + rl);
    outC[m0 * Hsz + j] = tanhf(acc00);
    outC[m0 * Hsz + j + 1] = tanhf(acc01);
    outC[(m0 + 1) * Hsz + j] = tanhf(acc10);
    outC[(m0 + 1) * Hsz + j + 1] = tanhf(acc11);
}

// ---------------- persistent recurrent kernel ----------------------------
// smem: W1/2/3 slices (96KB) + GRU slices (48KB) + 2 chunk buffers (64KB)
//       + reduction buffer (6KB)
#define SMEM_FLOATS (3 * 16 * H2 + 2 * 24 * Hsz + 2 * 64 * CH + 1536)
#define SMEM_BYTES (SMEM_FLOATS * 4)

__global__ void __launch_bounds__(NTHR, 1) rnn_kernel(
    const float* __restrict__ noise,
    const float* __restrict__ W1, const float* __restrict__ b1,
    const float* __restrict__ W2, const float* __restrict__ b2,
    const float* __restrict__ W3, const float* __restrict__ b3,
    const float* __restrict__ W4, const float* __restrict__ b4,
    const float* __restrict__ Wih, const float* __restrict__ Whh,
    const float* __restrict__ bih, const float* __restrict__ bhh,
    float* out)
{
    extern __shared__ float smem[];
    float* sW1 = smem;
    float* sW2 = sW1 + 16 * H2;
    float* sW3 = sW2 + 16 * H2;
    float* sWih = sW3 + 16 * H2;
    float* sWhh = sWih + 24 * Hsz;
    float* buf0 = sWhh + 24 * Hsz;
    float* buf1 = buf0 + 64 * CH;
    float* s_red = buf1 + 64 * CH;
    __shared__ float s_part[64];

    const int tid = threadIdx.x;
    const int blk = blockIdx.x;
    const int rg = blk >> 5, cg = blk & 31;
    const int r0 = rg * 64;
    const int j0 = cg * 16;
    const int jh0 = cg * 8;
    float* outC = out;
    float* outH = out + (size_t)Bsz * Tsz * Hsz;
    float* outF = outH + (size_t)Bsz * Tsz * Hsz;

    // ---- preload weight slices into SMEM (once) ----
    {
        const float* Wg[3] = {W1, W2, W3};
        float* sWd[3] = {sW1, sW2, sW3};
#pragma unroll 1
        for (int m = 0; m < 3; m++) {
            for (int i = tid; i < 2048; i += NTHR) {
                int col = i >> 7, k4 = i & 127;
                ((float4*)sWd[m])[col * 128 + k4] =
                    __ldg((const float4*)(Wg[m] + (size_t)(j0 + col) * H2) + k4);
            }
        }
        for (int i = tid; i < 1536; i += NTHR) {
            int rr = i >> 6, k4 = i & 63;
            int gte = rr >> 3, cl = rr & 7;
            size_t grow = (size_t)(gte * Hsz + jh0 + cl) * Hsz;
            ((float4*)sWih)[rr * 64 + k4] = __ldg((const float4*)(Wih + grow) + k4);
            ((float4*)sWhh)[rr * 64 + k4] = __ldg((const float4*)(Whh + grow) + k4);
        }
    }

    // ---- init state (each block owns batch rows 2blk, 2blk+1) ----
    {
        int b = 2 * blk + (tid >> 7);
        int j2 = (tid & 127) * 2;
        *(float2*)(&g_c[b * Hsz + j2]) = make_float2(0.f, 0.f);
        *(float2*)(&g_h[b * Hsz + j2]) = make_float2(0.f, 0.f);
        if ((tid & 127) == 0) { g_n[b] = 0.f; g_logit[b] = b4[0]; }
    }
    rg_sync(rg);

    const size_t cstr = (size_t)Tsz * Hsz;
#pragma unroll 1
    for (int t = 0; t < Tsz; t++) {
        // ---- stage 1: a1 = relu([c, c_in] @ W1^T + b1), then GRU(c,h) ----
        mlp_stage<1>(g_c, (size_t)Hsz, outC + (size_t)t * Hsz, cstr,
                     sW1, b1, (const float*)0, g_a1, buf0, buf1, s_red, s_part,
                     r0, j0, tid);
        gru_stage(sWih, sWhh, bih, bhh, buf0, buf1, s_red, r0, jh0, tid, g_gru);
        rg_sync(rg);
        // ---- stage 2: a2 ----
        mlp_stage<1>(g_a1, (size_t)H2, g_a1 + 256, (size_t)H2,
                     sW2, b2, (const float*)0, g_a2, buf0, buf1, s_red, s_part,
                     r0, j0, tid);
        rg_sync(rg);
        // ---- stage 3: a3 reduced against W4 -> logit ----
        if (tid < 64) s_part[tid] = 0.f;
        __syncthreads();
        mlp_stage<0>(g_a2, (size_t)H2, g_a2 + 256, (size_t)H2,
                     sW3, b3, W4, (float*)0, buf0, buf1, s_red, s_part,
                     r0, j0, tid);
        if (tid < 64) atomicAdd(&g_logit[r0 + tid], s_part[tid]);
        rg_sync(rg);
        // ---- stage 4: gate + state update (own 2 batch rows) ----
        {
            int b = 2 * blk + (tid >> 7);
            int j2 = (tid & 127) * 2;
            float logit = __ldcg(&g_logit[b]);
            float u = noise[(size_t)t * Bsz + b];
            float lg = logf(u) - log1pf(-u);
            float alpha = 1.f / (1.f + expf(-(logit + lg) * 10.f));
            float oma = 1.f - alpha;
            float nold = g_n[b];
            float nnew = nold * oma + 1.f;
            float inv = 1.f / nnew;
            float2 cin = *(const float2*)(outC + (size_t)b * cstr + (size_t)t * Hsz + j2);
            float2 cold = *(const float2*)(&g_c[b * Hsz + j2]);
            float2 hold = *(const float2*)(&g_h[b * Hsz + j2]);
            float2 gr = __ldcg((const float2*)(&g_gru[b * Hsz + j2]));
            float2 hnew, cnew;
            hnew.x = hold.x * oma + alpha * gr.x;
            hnew.y = hold.y * oma + alpha * gr.y;
            cnew.x = (cold.x * nold * oma + cin.x) * inv;
            cnew.y = (cold.y * nold * oma + cin.y) * inv;
            *(float2*)(&g_c[b * Hsz + j2]) = cnew;
            *(float2*)(&g_h[b * Hsz + j2]) = hnew;
            *(float2*)(&outH[(size_t)b * cstr + (size_t)t * Hsz + j2]) = hnew;
            __syncthreads();
            if ((tid & 127) == 0) { g_n[b] = nnew; g_logit[b] = b4[0]; }
        }
        rg_sync(rg);
    }
    // ---- h_final = GRUCell(c_T, h_T) ----
    gru_stage(sWih, sWhh, bih, bhh, buf0, buf1, s_red, r0, jh0, tid, outF);
}

extern "C" void kernel_launch(void* const* d_in, const int* in_sizes, int n_in,
                              void* d_out, int out_size)
{
    const float* input = (const float*)d_in[0];
    const float* noise = (const float*)d_in[1];
    const float* W_cin = (const float*)d_in[2];
    const float* b_cin = (const float*)d_in[3];
    const float* W1 = (const float*)d_in[4];
    const float* b1 = (const float*)d_in[5];
    const float* W2 = (const float*)d_in[6];
    const float* b2 = (const float*)d_in[7];
    const float* W3 = (const float*)d_in[8];
    const float* b3 = (const float*)d_in[9];
    const float* W4 = (const float*)d_in[10];
    const float* b4 = (const float*)d_in[11];
    const float* Wih = (const float*)d_in[12];
    const float* Whh = (const float*)d_in[13];
    const float* bih = (const float*)d_in[14];
    const float* bhh = (const float*)d_in[15];
    float* out = (float*)d_out;

    cudaFuncSetAttribute(rnn_kernel, cudaFuncAttributeMaxDynamicSharedMemorySize,
                         SMEM_BYTES);

    // c_concat = tanh(input @ W_cin^T + b_cin), written straight into d_out
    cin_kernel<<<(Bsz * Tsz / 64) * (Hsz / 16), CTHR>>>(input, W_cin, b_cin, out);
    // persistent recurrent kernel (reads c_concat back as the c_in stream)
    rnn_kernel<<<NBLK, NTHR, SMEM_BYTES>>>(noise, W1, b1, W2, b2, W3, b3, W4, b4,
                                           Wih, Whh, bih, bhh, out);
}